// round 17
// baseline (speedup 1.0000x reference)
#include <cuda_runtime.h>
#include <math.h>

constexpr int NB = 64;
constexpr int NT = 12;
constexpr int ND = 256;
constexpr int NS = 512;
constexpr int NV = 512;
constexpr int GRAPH_STEPS = 3;

typedef unsigned long long ull;

// cross-kernel scratch
__device__ float g_part[2][2 * NB * NT];   // gate partial sums [colhalf][...]
__device__ ull   g_gs2[32 * 512];          // [bpair][k] = (gsA, gsB)

__device__ __forceinline__ float gelu_f(float x) {
    return 0.5f * x * (1.0f + erff(x * 0.70710678118654752440f));
}
__device__ __forceinline__ float sigmoid_f(float x) {
    return 1.0f / (1.0f + expf(-x));
}

// ---- packed f32x2 helpers (sm_103a) ----
__device__ __forceinline__ ull pk2(float lo, float hi) {
    ull r; asm("mov.b64 %0, {%1, %2};" : "=l"(r) : "f"(lo), "f"(hi)); return r;
}
__device__ __forceinline__ ull fma2(ull a, ull b, ull c) {
    ull d; asm("fma.rn.f32x2 %0, %1, %2, %3;" : "=l"(d) : "l"(a), "l"(b), "l"(c)); return d;
}
__device__ __forceinline__ ull add2(ull a, ull b) {
    ull d; asm("add.rn.f32x2 %0, %1, %2;" : "=l"(d) : "l"(a), "l"(b)); return d;
}
__device__ __forceinline__ float2 upk(ull v) {
    float2 f; asm("mov.b64 {%0, %1}, %2;" : "=f"(f.x), "=f"(f.y) : "l"(v)); return f;
}

// ---------------------------------------------------------------------------
// Kernel A: gate MLPs, batch-pair packed, single-shot K-combine (proven R15).
// grid = 128 = bpair(32) x gate(2) x colhalf(2), 1024 threads, 96KB dyn smem.
// Also zeroes the output buffer for kernel C's atomic accumulation.
// ---------------------------------------------------------------------------
__global__ void __launch_bounds__(1024, 1)
k_gates(const float* __restrict__ evidence,
        const float* __restrict__ Wmg1, const float* __restrict__ bmg1,
        const float* __restrict__ Wmg2,
        const float* __restrict__ Wsg1, const float* __restrict__ bsg1,
        const float* __restrict__ Wsg2,
        float* __restrict__ out)
{
    extern __shared__ __align__(16) char ubuf[];   // 96KB dynamic
    __shared__ float red[2][NT][4];

    const int bid = blockIdx.x;
    const int p  = bid >> 2;
    const int g  = (bid >> 1) & 1;
    const int ch = bid & 1;
    const int bA = 2 * p;
    const int tid = threadIdx.x;

    if (tid < 384) out[bid * 384 + tid] = 0.f;

    const float* __restrict__ W1 = g ? Wsg1 : Wmg1;
    const float* __restrict__ B1 = g ? bsg1 : bmg1;
    const float* __restrict__ W2 = g ? Wsg2 : Wmg2;

    ull* ev2 = (ull*)ubuf;
    {
        const int k = tid & 255, q = tid >> 8;
        #pragma unroll
        for (int r = q * 3; r < q * 3 + 3; r++)
            ev2[k * NT + r] = pk2(evidence[(bA * NT + r) * ND + k],
                                  evidence[((bA + 1) * NT + r) * ND + k]);
    }
    __syncthreads();

    const int jp = tid & 127;
    const int kg = tid >> 7;
    const int j  = ch * 128 + jp;

    ull acc[NT];
    #pragma unroll
    for (int i = 0; i < NT; i++) acc[i] = 0ull;
    {
        const int k0 = kg * 32;
        #pragma unroll 8
        for (int kk = 0; kk < 32; kk++) {
            const int k = k0 + kk;
            const float w = W1[k * ND + j];
            const ull wp = pk2(w, w);
            const ulonglong2* xp = (const ulonglong2*)(ev2 + k * NT);
            {
                const ulonglong2 q0 = xp[0], q1 = xp[1], q2 = xp[2];
                acc[0] = fma2(q0.x, wp, acc[0]);
                acc[1] = fma2(q0.y, wp, acc[1]);
                acc[2] = fma2(q1.x, wp, acc[2]);
                acc[3] = fma2(q1.y, wp, acc[3]);
                acc[4] = fma2(q2.x, wp, acc[4]);
                acc[5] = fma2(q2.y, wp, acc[5]);
            }
            {
                const ulonglong2 q3 = xp[3], q4 = xp[4], q5 = xp[5];
                acc[6]  = fma2(q3.x, wp, acc[6]);
                acc[7]  = fma2(q3.y, wp, acc[7]);
                acc[8]  = fma2(q4.x, wp, acc[8]);
                acc[9]  = fma2(q4.y, wp, acc[9]);
                acc[10] = fma2(q5.x, wp, acc[10]);
                acc[11] = fma2(q5.y, wp, acc[11]);
            }
        }
    }
    __syncthreads();

    ull* comb = (ull*)ubuf;
    #pragma unroll
    for (int i = 0; i < NT; i++)
        comb[(kg * NT + i) * 128 + jp] = acc[i];
    __syncthreads();

    if (tid < 512) {
        const int jr = tid & 127;
        const int rg = tid >> 7;
        const int jc = ch * 128 + jr;
        const float b1 = B1[jc];
        const float w2 = W2[jc];
        const int lane = tid & 31;
        const int ws   = (tid >> 5) & 3;
        #pragma unroll
        for (int rr = 0; rr < 3; rr++) {
            const int r = rg * 3 + rr;
            ull s = comb[(0 * NT + r) * 128 + jr];
            #pragma unroll
            for (int k2 = 1; k2 < 8; k2++)
                s = add2(s, comb[(k2 * NT + r) * 128 + jr]);
            const float2 f = upk(s);
            float yA = gelu_f(f.x + b1) * w2;
            float yB = gelu_f(f.y + b1) * w2;
            #pragma unroll
            for (int off = 16; off > 0; off >>= 1) {
                yA += __shfl_xor_sync(0xffffffffu, yA, off);
                yB += __shfl_xor_sync(0xffffffffu, yB, off);
            }
            if (lane == 0) { red[0][r][ws] = yA; red[1][r][ws] = yB; }
        }
    }
    __syncthreads();

    if (tid < 24) {
        const int bsel = tid / NT, t = tid % NT;
        const float s = red[bsel][t][0] + red[bsel][t][1] + red[bsel][t][2] + red[bsel][t][3];
        g_part[ch][(g * NB + (2 * p + bsel)) * NT + t] = s;
    }
}

// ---------------------------------------------------------------------------
// Kernel B: sparse graph phase, one bpair per block (proven R12 body).
// grid = 32, 512 threads.  Writes g_gs2[p][k] = (gsA, gsB).
// ---------------------------------------------------------------------------
__global__ void __launch_bounds__(512, 2)
k_graph(const int* __restrict__ em,  const int* __restrict__ si,
        const int* __restrict__ sv,  const int* __restrict__ tsi,
        const int* __restrict__ tsv, const int* __restrict__ tvi,
        const int* __restrict__ tvv, const int* __restrict__ qi,
        const int* __restrict__ qv,
        const float* __restrict__ symbol_emb,
        const float* __restrict__ value_emb,
        const float* __restrict__ bmg2, const float* __restrict__ bsg2)
{
    __shared__ float walk[2][NS], nwalk[2][NS], wsum[2][NS], vw[2][NV];
    __shared__ float gate_s[2][2][NT];
    __shared__ int   e_msrc[2][NT], e_mtgt[2][NT], e_stgt[2][NT];
    __shared__ float e_mval[2][NT], e_sval[2][NT];
    __shared__ int   scand[2][16], vcand[2][16];
    __shared__ int   n_scand[2], n_vcand[2];

    const int p   = blockIdx.x;
    const int bA  = 2 * p;
    const int tid = threadIdx.x;

    {
        float* w0 = &walk[0][0];
        float* w1 = &wsum[0][0];
        float* w2 = &vw[0][0];
        w0[tid] = 0.f; w0[tid + 512] = 0.f;
        w1[tid] = 0.f; w1[tid + 512] = 0.f;
        w2[tid] = 0.f; w2[tid + 512] = 0.f;
    }
    if (tid < 48) {
        const int gg = tid / 24, rem = tid % 24;
        const int bsel = rem / NT, t = rem % NT;
        const int b = bA + bsel;
        const float b2 = gg ? bsg2[0] : bmg2[0];
        gate_s[gg][bsel][t] = sigmoid_f(g_part[0][(gg * NB + b) * NT + t]
                                      + g_part[1][(gg * NB + b) * NT + t] + b2);
    }
    if (tid >= 64 && tid < 88) {
        const int u = tid - 64;
        const int bsel = u / NT, t = u % NT;
        const int b = bA + bsel;
        const int mk  = em [b * NT + t];
        const int src = si [b * NT + t];
        const int svv = sv [b * NT + t];
        const int ts  = tsi[b * NT + t];
        const int tsx = tsv[b * NT + t];
        const int tv  = tvi[b * NT + t];
        const int tvx = tvv[b * NT + t];
        const int src_c = min(max(src, 0), NS - 1);
        const int ts_c  = min(max(ts,  0), NS - 1);
        const int tv_c  = min(max(tv,  0), NV - 1);
        const bool mm = ((mk == 0) || (mk == 1)) && (svv > 0) && (tvx > 0);
        const bool sm = (mk == 2) && (svv > 0) && (tsx > 0);
        e_msrc[bsel][t] = src_c; e_mtgt[bsel][t] = tv_c; e_mval[bsel][t] = mm ? 1.f : 0.f;
        e_stgt[bsel][t] = ts_c;  e_sval[bsel][t] = sm ? 1.f : 0.f;
    }
    __syncthreads();

    if (tid < 128) {
        const int w = tid >> 5, lane = tid & 31;
        const int bsel = w & 1;
        const bool is_s = (w < 2);
        const int b = bA + bsel;
        int cand = 0x10000 + lane;
        bool active = false;
        if (is_s) {
            if (lane == 0) {
                const int q = min(max(qi[b], 0), NS - 1);
                cand = q; active = true;
                if (qv[b] > 0) walk[bsel][q] = 1.0f;
            } else if (lane < 13) {
                cand = e_stgt[bsel][lane - 1]; active = true;
            }
        } else {
            if (lane < 12) { cand = e_mtgt[bsel][lane]; active = true; }
        }
        const unsigned m = __match_any_sync(0xffffffffu, cand);
        const bool keep = active && ((m & ((1u << lane) - 1u)) == 0u);
        const unsigned keepmask = __ballot_sync(0xffffffffu, keep);
        if (keep) {
            const int idx = __popc(keepmask & ((1u << lane) - 1u));
            if (is_s) scand[bsel][idx] = cand; else vcand[bsel][idx] = cand;
        }
        if (lane == 0) {
            if (is_s) n_scand[bsel] = __popc(keepmask);
            else      n_vcand[bsel] = __popc(keepmask);
        }
    }
    if (tid >= 128 && tid < 152) {
        const int u = tid - 128;
        const int bsel = u / NT, t = u % NT;
        e_mval[bsel][t] *= gate_s[0][bsel][t];
        e_sval[bsel][t] *= gate_s[1][bsel][t];
    }
    __syncthreads();

    if (tid < 64) {
        const int w = tid >> 5;
        const int lane = tid & 31;
        const int nsc = n_scand[w];
        for (int iter = 0; iter <= GRAPH_STEPS; iter++) {
            if (lane < nsc) wsum[w][scand[w][lane]] += walk[w][scand[w][lane]];
            if (lane < NT) {
                const float c = walk[w][e_msrc[w][lane]] * e_mval[w][lane];
                if (c != 0.f) atomicAdd(&vw[w][e_mtgt[w][lane]], c);
            }
            __syncwarp();
            if (iter < GRAPH_STEPS) {
                if (lane < nsc) nwalk[w][scand[w][lane]] = 0.f;
                __syncwarp();
                if (lane < NT) {
                    const float c = walk[w][e_msrc[w][lane]] * e_sval[w][lane];
                    if (c != 0.f) atomicAdd(&nwalk[w][e_stgt[w][lane]], c);
                }
                __syncwarp();
                if (lane < nsc) walk[w][scand[w][lane]] = nwalk[w][scand[w][lane]];
                __syncwarp();
            }
        }
    }
    __syncthreads();

    {
        float rA, rB;
        if (tid < 256) {
            const int d = tid;
            float a0 = 0.f, a1 = 0.f;
            const int n0 = n_scand[0], n1 = n_scand[1];
            for (int c = 0; c < n0; c++) {
                const int s = scand[0][c];
                a0 = fmaf(wsum[0][s], symbol_emb[s * ND + d], a0);
            }
            for (int c = 0; c < n1; c++) {
                const int s = scand[1][c];
                a1 = fmaf(wsum[1][s], symbol_emb[s * ND + d], a1);
            }
            rA = a0; rB = a1;
        } else {
            const int d = tid - 256;
            float a0 = 0.f, a1 = 0.f;
            const int n0 = n_vcand[0], n1 = n_vcand[1];
            for (int c = 0; c < n0; c++) {
                const int v = vcand[0][c];
                a0 = fmaf(vw[0][v], value_emb[v * ND + d], a0);
            }
            for (int c = 0; c < n1; c++) {
                const int v = vcand[1][c];
                a1 = fmaf(vw[1][v], value_emb[v * ND + d], a1);
            }
            rA = a0; rB = a1;
        }
        g_gs2[p * 512 + tid] = pk2(rA, rB);
    }
}

// ---------------------------------------------------------------------------
// Kernel C: output MLPs, 4-batch packed (2 bpairs per block).
// grid = 128 = bquad(16) x branch(2) x col-quarter(4), 1024 threads.
// Each weight LDG.64 feeds 4 FFMA2 (2 cols x 2 bpairs).
// Layer2 accumulates 4 quarter-contributions via atomicAdd into zeroed out.
// ---------------------------------------------------------------------------
__global__ void __launch_bounds__(1024, 1)
k_out4(const float* __restrict__ Wf1, const float* __restrict__ bf1,
       const float* __restrict__ Wf2, const float* __restrict__ bf2,
       const float* __restrict__ Wo1, const float* __restrict__ bo1,
       const float* __restrict__ Wo2, const float* __restrict__ bo2,
       float* __restrict__ out)
{
    __shared__ ull gs2s[1024];    // [bpsel][k]  8KB
    __shared__ ull h2s[128];      // [bpsel][64 local cols]  1KB
    __shared__ ull comb[4096];    // 32KB combine buffer

    const int bid = blockIdx.x;
    const int q   = bid >> 3;          // bquad: batches 4q..4q+3
    const int br  = (bid >> 2) & 1;    // 0 = feedback, 1 = logits
    const int cq  = bid & 3;           // col quarter
    const int tid = threadIdx.x;

    // load gs2 for both bpairs (contiguous 1024 ull)
    gs2s[tid] = g_gs2[q * 1024 + tid];
    __syncthreads();

    // ---- layer 1: 64-col quarter, full K=512, 4 batches ----
    const float* __restrict__ W1 = br ? Wo1 : Wf1;
    const float* __restrict__ B1 = br ? bo1 : bf1;
    {
        const int cp = tid & 31;       // col pair within quarter
        const int kg = tid >> 5;       // 0..31, 16 k each
        const int j0 = cq * 64 + 2 * cp;
        ull a00 = 0ull, a01 = 0ull, a10 = 0ull, a11 = 0ull;
        const int k0 = kg * 16;
        #pragma unroll 16
        for (int kk = 0; kk < 16; kk++) {
            const int k = k0 + kk;
            const float2 w = *(const float2*)&W1[k * ND + j0];
            const ull w0 = pk2(w.x, w.x), w1 = pk2(w.y, w.y);
            const ull av0 = gs2s[k];
            const ull av1 = gs2s[512 + k];
            a00 = fma2(av0, w0, a00);
            a01 = fma2(av0, w1, a01);
            a10 = fma2(av1, w0, a10);
            a11 = fma2(av1, w1, a11);
        }
        // comb layout [pay4][kg32][cp32], pay = bpsel*2 + colsel
        comb[(0 * 32 + kg) * 32 + cp] = a00;
        comb[(1 * 32 + kg) * 32 + cp] = a01;
        comb[(2 * 32 + kg) * 32 + cp] = a10;
        comb[(3 * 32 + kg) * 32 + cp] = a11;
    }
    __syncthreads();
    if (tid < 128) {
        const int cp2 = tid & 31, pay = tid >> 5;
        ull s = comb[(pay * 32 + 0) * 32 + cp2];
        #pragma unroll
        for (int kg2 = 1; kg2 < 32; kg2++)
            s = add2(s, comb[(pay * 32 + kg2) * 32 + cp2]);
        const int bpsel = pay >> 1, colsel = pay & 1;
        const int lcol = 2 * cp2 + colsel;
        const int col  = cq * 64 + lcol;
        const float2 f = upk(s);
        const float bb = B1[col];
        h2s[bpsel * 64 + lcol] = pk2(gelu_f(f.x + bb), gelu_f(f.y + bb));
    }
    __syncthreads();

    // ---- layer 2: K = this block's 64 h entries, all output cols ----
    if (br) {
        // logits: 512 cols -> 256 col-pairs; kg 4 x 16 k
        const int cp = tid & 255;
        const int kg = tid >> 8;
        const int j0 = 2 * cp;
        ull a00 = 0ull, a01 = 0ull, a10 = 0ull, a11 = 0ull;
        const int k0 = kg * 16;
        #pragma unroll 16
        for (int kk = 0; kk < 16; kk++) {
            const int k = k0 + kk;
            const float2 w = *(const float2*)&Wo2[(cq * 64 + k) * NV + j0];
            const ull w0 = pk2(w.x, w.x), w1 = pk2(w.y, w.y);
            const ull av0 = h2s[k];
            const ull av1 = h2s[64 + k];
            a00 = fma2(av0, w0, a00);
            a01 = fma2(av0, w1, a01);
            a10 = fma2(av1, w0, a10);
            a11 = fma2(av1, w1, a11);
        }
        // comb layout [pay4][kg4][cp256]
        comb[(0 * 4 + kg) * 256 + cp] = a00;
        comb[(1 * 4 + kg) * 256 + cp] = a01;
        comb[(2 * 4 + kg) * 256 + cp] = a10;
        comb[(3 * 4 + kg) * 256 + cp] = a11;
        __syncthreads();
        {
            const int cp2 = tid & 255, pay = tid >> 8;
            ull s = comb[(pay * 4 + 0) * 256 + cp2];
            #pragma unroll
            for (int kg2 = 1; kg2 < 4; kg2++)
                s = add2(s, comb[(pay * 4 + kg2) * 256 + cp2]);
            const int bpsel = pay >> 1, colsel = pay & 1;
            const int col = 2 * cp2 + colsel;
            float2 f = upk(s);
            if (cq == 0) { const float bb = bo2[col]; f.x += bb; f.y += bb; }
            const int b0 = 4 * q + 2 * bpsel;
            atomicAdd(&out[b0 * NV + col], f.x);
            atomicAdd(&out[(b0 + 1) * NV + col], f.y);
        }
    } else {
        // feedback: 256 cols -> 128 col-pairs; kg 8 x 8 k
        const int cp = tid & 127;
        const int kg = tid >> 7;
        const int j0 = 2 * cp;
        ull a00 = 0ull, a01 = 0ull, a10 = 0ull, a11 = 0ull;
        const int k0 = kg * 8;
        #pragma unroll 8
        for (int kk = 0; kk < 8; kk++) {
            const int k = k0 + kk;
            const float2 w = *(const float2*)&Wf2[(cq * 64 + k) * ND + j0];
            const ull w0 = pk2(w.x, w.x), w1 = pk2(w.y, w.y);
            const ull av0 = h2s[k];
            const ull av1 = h2s[64 + k];
            a00 = fma2(av0, w0, a00);
            a01 = fma2(av0, w1, a01);
            a10 = fma2(av1, w0, a10);
            a11 = fma2(av1, w1, a11);
        }
        // comb layout [pay4][kg8][cp128]
        comb[(0 * 8 + kg) * 128 + cp] = a00;
        comb[(1 * 8 + kg) * 128 + cp] = a01;
        comb[(2 * 8 + kg) * 128 + cp] = a10;
        comb[(3 * 8 + kg) * 128 + cp] = a11;
        __syncthreads();
        if (tid < 512) {
            const int cp2 = tid & 127, pay = tid >> 7;
            ull s = comb[(pay * 8 + 0) * 128 + cp2];
            #pragma unroll
            for (int kg2 = 1; kg2 < 8; kg2++)
                s = add2(s, comb[(pay * 8 + kg2) * 128 + cp2]);
            const int bpsel = pay >> 1, colsel = pay & 1;
            const int col = 2 * cp2 + colsel;
            float2 f = upk(s);
            if (cq == 0) { const float bb = bf2[col]; f.x += bb; f.y += bb; }
            const int b0 = 4 * q + 2 * bpsel;
            atomicAdd(&out[NB * NV + b0 * ND + col], f.x);
            atomicAdd(&out[NB * NV + (b0 + 1) * ND + col], f.y);
        }
    }
}

// ---------------------------------------------------------------------------
extern "C" void kernel_launch(void* const* d_in, const int* in_sizes, int n_in,
                              void* d_out, int out_size)
{
    const int*   event_marker       = (const int*)  d_in[0];
    const int*   source_idx         = (const int*)  d_in[1];
    const int*   source_valid       = (const int*)  d_in[2];
    const int*   target_symbol_idx  = (const int*)  d_in[3];
    const int*   target_symbol_vld  = (const int*)  d_in[4];
    const int*   target_value_idx   = (const int*)  d_in[5];
    const int*   target_value_vld   = (const int*)  d_in[6];
    const int*   query_idx          = (const int*)  d_in[7];
    const int*   query_valid        = (const int*)  d_in[8];
    const float* evidence           = (const float*)d_in[9];
    const float* symbol_emb         = (const float*)d_in[10];
    const float* value_emb          = (const float*)d_in[11];
    const float* Wmg1 = (const float*)d_in[12];
    const float* bmg1 = (const float*)d_in[13];
    const float* Wmg2 = (const float*)d_in[14];
    const float* bmg2 = (const float*)d_in[15];
    const float* Wsg1 = (const float*)d_in[16];
    const float* bsg1 = (const float*)d_in[17];
    const float* Wsg2 = (const float*)d_in[18];
    const float* bsg2 = (const float*)d_in[19];
    const float* Wf1  = (const float*)d_in[20];
    const float* bf1  = (const float*)d_in[21];
    const float* Wf2  = (const float*)d_in[22];
    const float* bf2  = (const float*)d_in[23];
    const float* Wo1  = (const float*)d_in[24];
    const float* bo1  = (const float*)d_in[25];
    const float* Wo2  = (const float*)d_in[26];
    const float* bo2  = (const float*)d_in[27];

    float* out = (float*)d_out;

    const int smem_bytes = 8 * NT * 128 * (int)sizeof(ull);   // 96KB
    cudaFuncSetAttribute(k_gates, cudaFuncAttributeMaxDynamicSharedMemorySize,
                         smem_bytes);

    k_gates<<<128, 1024, smem_bytes>>>(evidence, Wmg1, bmg1, Wmg2,
                                       Wsg1, bsg1, Wsg2, out);
    k_graph<<<32, 512>>>(event_marker, source_idx, source_valid,
                         target_symbol_idx, target_symbol_vld,
                         target_value_idx, target_value_vld,
                         query_idx, query_valid,
                         symbol_emb, value_emb, bmg2, bsg2);
    k_out4<<<128, 1024>>>(Wf1, bf1, Wf2, bf2,
                          Wo1, bo1, Wo2, bo2, out);
}